// round 11
// baseline (speedup 1.0000x reference)
#include <cuda_runtime.h>
#include <cuda_fp16.h>
#include <math.h>
#include <stdint.h>

// ---------------- problem constants ----------------
#define Bsz 16
#define Nn  16384
#define Cc  128            // C_IN == C_OUT
#define Ffull 1152         // 9 * 128
#define Mm  (Bsz * Nn)     // 262144 rows

// ---------------- static device scratch (fp16) ----------------
__device__ __half g_flat_h[(size_t)Mm * Ffull];
__device__ __half g_x_h[(size_t)Mm * Cc];
__device__ __half g_Wc_h[Cc * Ffull];
__device__ __half g_Ws_h[Cc * Cc];

typedef unsigned long long ull;

// ---------------- helpers ----------------
__device__ __forceinline__ uint32_t smem_u32(const void* p) {
    uint32_t a;
    asm("{ .reg .u64 t; cvta.to.shared.u64 t, %1; cvt.u32.u64 %0, t; }" : "=r"(a) : "l"(p));
    return a;
}
__device__ __forceinline__ void cp16(uint32_t dst, const void* src) {
    asm volatile("cp.async.cg.shared.global [%0], [%1], 16;" :: "r"(dst), "l"(src) : "memory");
}
#define CP_COMMIT() asm volatile("cp.async.commit_group;" ::: "memory")
#define CP_WAIT(n)  asm volatile("cp.async.wait_group %0;" :: "n"(n) : "memory")

__device__ __forceinline__ void ldsm4(uint32_t& d0, uint32_t& d1, uint32_t& d2, uint32_t& d3, uint32_t a) {
    asm volatile("ldmatrix.sync.aligned.m8n8.x4.shared.b16 {%0,%1,%2,%3}, [%4];"
                 : "=r"(d0), "=r"(d1), "=r"(d2), "=r"(d3) : "r"(a));
}
__device__ __forceinline__ void mma16816(float* c, const uint32_t* a, const uint32_t* b) {
    asm volatile("mma.sync.aligned.m16n8k16.row.col.f32.f16.f16.f32 "
                 "{%0,%1,%2,%3},{%4,%5,%6,%7},{%8,%9},{%0,%1,%2,%3};"
                 : "+f"(c[0]), "+f"(c[1]), "+f"(c[2]), "+f"(c[3])
                 : "r"(a[0]), "r"(a[1]), "r"(a[2]), "r"(a[3]), "r"(b[0]), "r"(b[1]));
}
// packed f32x2 FMA: d = a*b + d (per 32-bit lane, IEEE fp32 semantics)
__device__ __forceinline__ void fma2(ull& d, ull a, ull b) {
    asm("fma.rn.f32x2 %0, %1, %2, %0;" : "+l"(d) : "l"(a), "l"(b));
}
__device__ __forceinline__ ull pack2(float lo, float hi) {
    ull r;
    asm("mov.b64 %0,{%1,%2};" : "=l"(r) : "r"(__float_as_uint(lo)), "r"(__float_as_uint(hi)));
    return r;
}
__device__ __forceinline__ float2 unpack2(ull v) {
    unsigned lo, hi;
    asm("mov.b64 {%0,%1},%2;" : "=r"(lo), "=r"(hi) : "l"(v));
    return make_float2(__uint_as_float(lo), __uint_as_float(hi));
}
// fast elu: MUFU-based __expf; abs error ~2e-7 << fp16 rounding of same values
__device__ __forceinline__ float elu1(float v) { return (v > 0.f) ? v : (__expf(v) - 1.f); }
__device__ __forceinline__ uint32_t h2u(__half2 h) { return *(uint32_t*)&h; }

// ---------------- pass 0: convert weights / x to fp16 ----------------
__global__ void cvt_w(const float* __restrict__ Wc, const float* __restrict__ Ws) {
    int i = blockIdx.x * 256 + threadIdx.x;
    if (i < Cc * Ffull) g_Wc_h[i] = __float2half_rn(Wc[i]);
    if (i < Cc * Cc)    g_Ws_h[i] = __float2half_rn(Ws[i]);
}
__global__ __launch_bounds__(256) void cvt_x(const float* __restrict__ x) {
    size_t i4 = (size_t)blockIdx.x * 256 + threadIdx.x;   // index over float4s
    if (i4 >= (size_t)Mm * Cc / 4) return;
    float4 v = *(const float4*)(x + i4 * 4);
    uint2 o;
    o.x = h2u(__float22half2_rn(make_float2(v.x, v.y)));
    o.y = h2u(__float22half2_rn(make_float2(v.z, v.w)));
    *(uint2*)(g_x_h + i4 * 4) = o;
}

// ---------------- pass 1: gather(fp16) + packed-f32x2 P-mix + elu -> g_flat ----------------
// 256 threads / node: tid&15 -> 8-channel group, tid>>4 -> batch. One (node,b,ch8) per thread.
__global__ __launch_bounds__(256) void build_flat(
    const int* __restrict__ idx, const float* __restrict__ P)
{
    const int n = blockIdx.x;
    const int tid = threadIdx.x;
    const int c8 = (tid & 15) * 8;
    const int b  = tid >> 4;                 // 0..15

    __shared__ float2 Ps2[81];               // packed (p, p) for f32x2 broadcast
    __shared__ int    is[9];
    if (tid < 81) { float p = P[(size_t)n * 81 + tid]; Ps2[tid] = make_float2(p, p); }
    if (tid < 9)  is[tid] = idx[n * 9 + tid];
    __syncthreads();

    // gather 9 neighbour rows (8 fp16 each), unpack to packed f32x2
    ull nb[9][4];
#pragma unroll
    for (int j = 0; j < 9; j++) {
        uint4 raw = *(const uint4*)&g_x_h[((size_t)b * Nn + is[j]) * Cc + c8];
        float2 f0 = __half22float2(*(__half2*)&raw.x);
        float2 f1 = __half22float2(*(__half2*)&raw.y);
        float2 f2 = __half22float2(*(__half2*)&raw.z);
        float2 f3 = __half22float2(*(__half2*)&raw.w);
        nb[j][0] = pack2(f0.x, f0.y);
        nb[j][1] = pack2(f1.x, f1.y);
        nb[j][2] = pack2(f2.x, f2.y);
        nb[j][3] = pack2(f3.x, f3.y);
    }

    const size_t base = ((size_t)b * Nn + n) * Ffull + c8;
#pragma unroll
    for (int k = 0; k < 9; k++) {
        ull v0 = 0ull, v1 = 0ull, v2 = 0ull, v3 = 0ull;
#pragma unroll
        for (int j = 0; j < 9; j++) {
            ull pp = *(const ull*)&Ps2[k * 9 + j];   // LDS.64 broadcast
            fma2(v0, pp, nb[j][0]);
            fma2(v1, pp, nb[j][1]);
            fma2(v2, pp, nb[j][2]);
            fma2(v3, pp, nb[j][3]);
        }
        float2 f0 = unpack2(v0), f1 = unpack2(v1), f2 = unpack2(v2), f3 = unpack2(v3);
        uint4 o;
        o.x = h2u(__floats2half2_rn(elu1(f0.x), elu1(f0.y)));
        o.y = h2u(__floats2half2_rn(elu1(f1.x), elu1(f1.y)));
        o.z = h2u(__floats2half2_rn(elu1(f2.x), elu1(f2.y)));
        o.w = h2u(__floats2half2_rn(elu1(f3.x), elu1(f3.y)));
        *(uint4*)(g_flat_h + base + (size_t)k * Cc) = o;
    }
}

// ---------------- pass 2: single-fp16 mma.sync GEMM, fused epilogue ----------------
#define NCH     20
#define NCONV   18
#define TILE_B  16384                 // 128 rows x 128 bytes (64 fp16)
#define STAGE_B (2 * TILE_B)          // A, B = 32KB
#define NSTAGE  3
#define SMEM_B  (NSTAGE * STAGE_B)    // 98304

// swizzled offset for (row r, 16B-granule g in 0..7), 128B rows
#define SWO(r, g) ((uint32_t)(r) * 128u + (uint32_t)((((g) ^ ((r) & 7))) << 4))

__global__ __launch_bounds__(256, 2) void gemm_mma(
    const float* __restrict__ bconv, const float* __restrict__ bskip,
    float* __restrict__ out)
{
    extern __shared__ char smem[];
    const uint32_t sb = smem_u32(smem);
    const int tid = threadIdx.x;
    const int lane = tid & 31, wid = tid >> 5;
    const int warpM = wid >> 2, warpN = wid & 3;      // 2 x 4 warp grid
    const size_t mrow0 = (size_t)blockIdx.x * 128;

    // ---- loader: precomputed dsts + advancing src pointers ----
    const int lrw = tid >> 3, lgw = tid & 7;          // 32 rows x 8 granules per wave
    uint32_t sdst[4];
    const __half* pa[4]; const __half* pb[4];         // advancing conv srcs
    const __half* aS[4]; const __half* bS[4];         // skip srcs
#pragma unroll
    for (int i = 0; i < 4; i++) {
        int r = i * 32 + lrw;
        sdst[i] = SWO(r, lgw);
        pa[i] = g_flat_h + (mrow0 + r) * (size_t)Ffull + lgw * 8;
        pb[i] = g_Wc_h   + (size_t)r * Ffull          + lgw * 8;
        aS[i] = g_x_h    + (mrow0 + r) * (size_t)Cc   + lgw * 8;
        bS[i] = g_Ws_h   + (size_t)r * Cc             + lgw * 8;
    }

    auto issue = [&](int t, int s) {
        const uint32_t st = sb + (uint32_t)s * STAGE_B;
        if (t < NCONV) {
#pragma unroll
            for (int i = 0; i < 4; i++) {
                cp16(st + sdst[i],          pa[i]);
                cp16(st + sdst[i] + TILE_B, pb[i]);
                pa[i] += 64; pb[i] += 64;
            }
        } else {
            const int off = (t - NCONV) * 64;
#pragma unroll
            for (int i = 0; i < 4; i++) {
                cp16(st + sdst[i],          aS[i] + off);
                cp16(st + sdst[i] + TILE_B, bS[i] + off);
            }
        }
        CP_COMMIT();
    };

    // ---- fragment address components ----
    const int lr = lane & 15, lg = lane >> 4;
    uint32_t arow[4], brow[2];
    int ax7[4], bx7[2];
#pragma unroll
    for (int mi = 0; mi < 4; mi++) {
        int r = warpM * 64 + mi * 16 + lr;
        arow[mi] = (uint32_t)r * 128u; ax7[mi] = r & 7;
    }
#pragma unroll
    for (int np = 0; np < 2; np++) {
        int r = warpN * 32 + np * 16 + lr;
        brow[np] = (uint32_t)r * 128u; bx7[np] = r & 7;
    }

    float acc[4][4][4];
#pragma unroll
    for (int mi = 0; mi < 4; mi++)
#pragma unroll
        for (int ni = 0; ni < 4; ni++)
#pragma unroll
            for (int j = 0; j < 4; j++) acc[mi][ni][j] = 0.f;

    issue(0, 0); issue(1, 1);

    for (int t = 0; t < NCH; t++) {
        if (t + 1 < NCH) CP_WAIT(1); else CP_WAIT(0);
        __syncthreads();
        if (t + 2 < NCH) issue(t + 2, (t + 2) % NSTAGE);   // overlaps compute below

        const uint32_t st = sb + (uint32_t)(t % NSTAGE) * STAGE_B;
#pragma unroll
        for (int kk = 0; kk < 4; kk++) {
            const int g = kk * 2 + lg;
            uint32_t Af[4][4], Bf[4][2];
#pragma unroll
            for (int mi = 0; mi < 4; mi++) {
                uint32_t o = st + arow[mi] + (uint32_t)((g ^ ax7[mi]) << 4);
                ldsm4(Af[mi][0], Af[mi][1], Af[mi][2], Af[mi][3], o);
            }
#pragma unroll
            for (int np = 0; np < 2; np++) {
                uint32_t o = st + TILE_B + brow[np] + (uint32_t)((g ^ bx7[np]) << 4);
                uint32_t h0, h1, h2, h3;
                ldsm4(h0, h1, h2, h3, o);
                Bf[np * 2 + 0][0] = h0; Bf[np * 2 + 0][1] = h2;
                Bf[np * 2 + 1][0] = h1; Bf[np * 2 + 1][1] = h3;
            }
#pragma unroll
            for (int mi = 0; mi < 4; mi++)
#pragma unroll
                for (int ni = 0; ni < 4; ni++)
                    mma16816(acc[mi][ni], Af[mi], Bf[ni]);
        }

        if (t == NCONV - 1) {
            // conv done: acc = elu(acc + b_conv); skip chunks then accumulate on top
#pragma unroll
            for (int ni = 0; ni < 4; ni++) {
                int col = warpN * 32 + ni * 8 + 2 * (lane & 3);
                float b0 = __ldg(bconv + col), b1 = __ldg(bconv + col + 1);
#pragma unroll
                for (int mi = 0; mi < 4; mi++) {
                    acc[mi][ni][0] = elu1(acc[mi][ni][0] + b0);
                    acc[mi][ni][1] = elu1(acc[mi][ni][1] + b1);
                    acc[mi][ni][2] = elu1(acc[mi][ni][2] + b0);
                    acc[mi][ni][3] = elu1(acc[mi][ni][3] + b1);
                }
            }
        }
    }

    // ---- epilogue: out = acc + b_skip ----
#pragma unroll
    for (int ni = 0; ni < 4; ni++) {
        int col = warpN * 32 + ni * 8 + 2 * (lane & 3);
        float b0 = __ldg(bskip + col), b1 = __ldg(bskip + col + 1);
#pragma unroll
        for (int mi = 0; mi < 4; mi++) {
            size_t r0 = mrow0 + warpM * 64 + mi * 16 + (lane >> 2);
            float2 v0 = make_float2(acc[mi][ni][0] + b0, acc[mi][ni][1] + b1);
            float2 v1 = make_float2(acc[mi][ni][2] + b0, acc[mi][ni][3] + b1);
            *(float2*)&out[r0 * Cc + col]       = v0;
            *(float2*)&out[(r0 + 8) * Cc + col] = v1;
        }
    }
}

// ---------------- launch ----------------
extern "C" void kernel_launch(void* const* d_in, const int* in_sizes, int n_in,
                              void* d_out, int out_size)
{
    const float* x   = (const float*)d_in[0];
    const int*   idx = (const int*)  d_in[1];
    const float* P   = (const float*)d_in[2];
    const float* Wc  = (const float*)d_in[3];
    const float* bc  = (const float*)d_in[4];
    const float* Ws  = (const float*)d_in[5];
    const float* bs  = (const float*)d_in[6];
    float* out = (float*)d_out;
    (void)in_sizes; (void)n_in; (void)out_size;

    cudaFuncSetAttribute(gemm_mma, cudaFuncAttributeMaxDynamicSharedMemorySize, SMEM_B);

    cvt_x<<<(int)(((size_t)Mm * Cc / 4 + 255) / 256), 256>>>(x);   // must precede build_flat
    cvt_w<<<(Cc * Ffull + 255) / 256, 256>>>(Wc, Ws);
    build_flat<<<Nn, 256>>>(idx, P);
    gemm_mma<<<Mm / 128, 256, SMEM_B>>>(bc, bs, out);
}

// round 12
// speedup vs baseline: 1.4187x; 1.4187x over previous
#include <cuda_runtime.h>
#include <cuda_fp16.h>
#include <math.h>
#include <stdint.h>

// ---------------- problem constants ----------------
#define Bsz 16
#define Nn  16384
#define Cc  128            // C_IN == C_OUT
#define Ffull 1152         // 9 * 128
#define Mm  (Bsz * Nn)     // 262144 rows

// ---------------- static device scratch (fp16) ----------------
__device__ __half g_flat_h[(size_t)Mm * Ffull];   // CTA-local round-trip (L2-hot)
__device__ __half g_x_h[(size_t)Mm * Cc];
__device__ __half g_Wc_h[Cc * Ffull];
__device__ __half g_Ws_h[Cc * Cc];

// ---------------- helpers ----------------
__device__ __forceinline__ uint32_t smem_u32(const void* p) {
    uint32_t a;
    asm("{ .reg .u64 t; cvta.to.shared.u64 t, %1; cvt.u32.u64 %0, t; }" : "=r"(a) : "l"(p));
    return a;
}
__device__ __forceinline__ void cp16(uint32_t dst, const void* src) {
    asm volatile("cp.async.cg.shared.global [%0], [%1], 16;" :: "r"(dst), "l"(src) : "memory");
}
#define CP_COMMIT() asm volatile("cp.async.commit_group;" ::: "memory")
#define CP_WAIT(n)  asm volatile("cp.async.wait_group %0;" :: "n"(n) : "memory")

__device__ __forceinline__ void ldsm4(uint32_t& d0, uint32_t& d1, uint32_t& d2, uint32_t& d3, uint32_t a) {
    asm volatile("ldmatrix.sync.aligned.m8n8.x4.shared.b16 {%0,%1,%2,%3}, [%4];"
                 : "=r"(d0), "=r"(d1), "=r"(d2), "=r"(d3) : "r"(a));
}
__device__ __forceinline__ void mma16816(float* c, const uint32_t* a, const uint32_t* b) {
    asm volatile("mma.sync.aligned.m16n8k16.row.col.f32.f16.f16.f32 "
                 "{%0,%1,%2,%3},{%4,%5,%6,%7},{%8,%9},{%0,%1,%2,%3};"
                 : "+f"(c[0]), "+f"(c[1]), "+f"(c[2]), "+f"(c[3])
                 : "r"(a[0]), "r"(a[1]), "r"(a[2]), "r"(a[3]), "r"(b[0]), "r"(b[1]));
}
// fast elu (validated in R10: abs err ~2e-7 << fp16 rounding of same values)
__device__ __forceinline__ float elu1(float v) { return (v > 0.f) ? v : (__expf(v) - 1.f); }
__device__ __forceinline__ uint32_t h2u(__half2 h) { return *(uint32_t*)&h; }

// ---------------- pass 0: convert weights / x to fp16 ----------------
__global__ void cvt_w(const float* __restrict__ Wc, const float* __restrict__ Ws) {
    int i = blockIdx.x * 256 + threadIdx.x;
    if (i < Cc * Ffull) g_Wc_h[i] = __float2half_rn(Wc[i]);
    if (i < Cc * Cc)    g_Ws_h[i] = __float2half_rn(Ws[i]);
}
__global__ __launch_bounds__(256) void cvt_x(const float* __restrict__ x) {
    size_t i4 = (size_t)blockIdx.x * 256 + threadIdx.x;
    if (i4 >= (size_t)Mm * Cc / 4) return;
    float4 v = *(const float4*)(x + i4 * 4);
    uint2 o;
    o.x = h2u(__float22half2_rn(make_float2(v.x, v.y)));
    o.y = h2u(__float22half2_rn(make_float2(v.z, v.w)));
    *(uint2*)(g_x_h + i4 * 4) = o;
}

// ---------------- fused kernel: build own flat rows, then mma GEMM ----------------
#define NCH     20
#define NCONV   18
#define TILE_B  16384                 // 128 rows x 128 bytes (64 fp16)
#define STAGE_B (2 * TILE_B)          // A, B = 32KB
#define NSTAGE  3
#define SMEM_B  (NSTAGE * STAGE_B)    // 98304 (P/idx slabs alias the low 46KB)

// swizzled offset for (row r, 16B-granule g in 0..7), 128B rows
#define SWO(r, g) ((uint32_t)(r) * 128u + (uint32_t)((((g) ^ ((r) & 7))) << 4))

__global__ __launch_bounds__(256, 2) void fused_mma(
    const int* __restrict__ idx, const float* __restrict__ P,
    const float* __restrict__ bconv, const float* __restrict__ bskip,
    float* __restrict__ out)
{
    extern __shared__ char smem[];
    const uint32_t sb = smem_u32(smem);
    const int tid = threadIdx.x;
    const int lane = tid & 31, wid = tid >> 5;
    const int warpM = wid >> 2, warpN = wid & 3;       // 2 x 4 warp grid
    const size_t mrow0 = (size_t)blockIdx.x * 128;     // = b*Nn + n0
    const int b  = blockIdx.x >> 7;
    const int n0 = (blockIdx.x & 127) << 7;

    // ================= phase 1: build this CTA's 128 flat rows =================
    // smem alias (strictly before any cp.async into the pipeline region):
    float* sP  = (float*)smem;                 // 128*81*4 = 41472 B
    int* sidx  = (int*)(smem + 41472);         // 128*9*4  =  4608 B  (total 46080 < SMEM_B)
    for (int i = tid; i < 128 * 81; i += 256) sP[i] = P[(size_t)n0 * 81 + i];
    for (int i = tid; i < 128 * 9;  i += 256) sidx[i] = idx[n0 * 9 + i];
    __syncthreads();

    {
        const int c4 = (lane) * 4;             // warp spans all 128 channels
        const int nq = tid >> 5;               // warp -> node strip
        for (int ii = 0; ii < 16; ii++) {
            const int i = nq * 16 + ii;        // node within CTA (all lanes same i)
            float4 nb[9];
#pragma unroll
            for (int j = 0; j < 9; j++) {
                uint2 raw = *(const uint2*)&g_x_h[((size_t)b * Nn + sidx[i * 9 + j]) * Cc + c4];
                float2 f01 = __half22float2(*(__half2*)&raw.x);
                float2 f23 = __half22float2(*(__half2*)&raw.y);
                nb[j] = make_float4(f01.x, f01.y, f23.x, f23.y);
            }
            const float* Pn = sP + i * 81;     // LDS broadcast across warp
            const size_t gbase = (mrow0 + i) * Ffull + c4;
#pragma unroll
            for (int k = 0; k < 9; k++) {
                float v0 = 0.f, v1 = 0.f, v2 = 0.f, v3 = 0.f;
#pragma unroll
                for (int j = 0; j < 9; j++) {
                    float p = Pn[k * 9 + j];
                    v0 = fmaf(p, nb[j].x, v0);
                    v1 = fmaf(p, nb[j].y, v1);
                    v2 = fmaf(p, nb[j].z, v2);
                    v3 = fmaf(p, nb[j].w, v3);
                }
                uint2 o;
                o.x = h2u(__floats2half2_rn(elu1(v0), elu1(v1)));
                o.y = h2u(__floats2half2_rn(elu1(v2), elu1(v3)));
                *(uint2*)(g_flat_h + gbase + (size_t)k * Cc) = o;
            }
        }
    }
    __threadfence_block();
    __syncthreads();   // block-scope fence: our STGs visible to our cp.async reads

    // ================= phase 2: mma GEMM (reads back L2-hot flat rows) =================
    const int lrw = tid >> 3, lgw = tid & 7;
    uint32_t sdst[4];
    const __half* pa[4]; const __half* pb[4];          // advancing conv srcs
    const __half* aS[4]; const __half* bS[4];          // skip srcs
#pragma unroll
    for (int i = 0; i < 4; i++) {
        int r = i * 32 + lrw;
        sdst[i] = SWO(r, lgw);
        pa[i] = g_flat_h + (mrow0 + r) * (size_t)Ffull + lgw * 8;
        pb[i] = g_Wc_h   + (size_t)r * Ffull          + lgw * 8;
        aS[i] = g_x_h    + (mrow0 + r) * (size_t)Cc   + lgw * 8;
        bS[i] = g_Ws_h   + (size_t)r * Cc             + lgw * 8;
    }

    auto issue = [&](int t, int s) {
        const uint32_t st = sb + (uint32_t)s * STAGE_B;
        if (t < NCONV) {
#pragma unroll
            for (int i = 0; i < 4; i++) {
                cp16(st + sdst[i],          pa[i]);
                cp16(st + sdst[i] + TILE_B, pb[i]);
                pa[i] += 64; pb[i] += 64;
            }
        } else {
            const int off = (t - NCONV) * 64;
#pragma unroll
            for (int i = 0; i < 4; i++) {
                cp16(st + sdst[i],          aS[i] + off);
                cp16(st + sdst[i] + TILE_B, bS[i] + off);
            }
        }
        CP_COMMIT();
    };

    const int lr = lane & 15, lg = lane >> 4;
    uint32_t arow[4], brow[2];
    int ax7[4], bx7[2];
#pragma unroll
    for (int mi = 0; mi < 4; mi++) {
        int r = warpM * 64 + mi * 16 + lr;
        arow[mi] = (uint32_t)r * 128u; ax7[mi] = r & 7;
    }
#pragma unroll
    for (int np = 0; np < 2; np++) {
        int r = warpN * 32 + np * 16 + lr;
        brow[np] = (uint32_t)r * 128u; bx7[np] = r & 7;
    }

    float acc[4][4][4];
#pragma unroll
    for (int mi = 0; mi < 4; mi++)
#pragma unroll
        for (int ni = 0; ni < 4; ni++)
#pragma unroll
            for (int j = 0; j < 4; j++) acc[mi][ni][j] = 0.f;

    issue(0, 0); issue(1, 1);

    for (int t = 0; t < NCH; t++) {
        if (t + 1 < NCH) CP_WAIT(1); else CP_WAIT(0);
        __syncthreads();
        if (t + 2 < NCH) issue(t + 2, (t + 2) % NSTAGE);

        const uint32_t st = sb + (uint32_t)(t % NSTAGE) * STAGE_B;
#pragma unroll
        for (int kk = 0; kk < 4; kk++) {
            const int g = kk * 2 + lg;
            uint32_t Af[4][4], Bf[4][2];
#pragma unroll
            for (int mi = 0; mi < 4; mi++) {
                uint32_t o = st + arow[mi] + (uint32_t)((g ^ ax7[mi]) << 4);
                ldsm4(Af[mi][0], Af[mi][1], Af[mi][2], Af[mi][3], o);
            }
#pragma unroll
            for (int np = 0; np < 2; np++) {
                uint32_t o = st + TILE_B + brow[np] + (uint32_t)((g ^ bx7[np]) << 4);
                uint32_t h0, h1, h2, h3;
                ldsm4(h0, h1, h2, h3, o);
                Bf[np * 2 + 0][0] = h0; Bf[np * 2 + 0][1] = h2;
                Bf[np * 2 + 1][0] = h1; Bf[np * 2 + 1][1] = h3;
            }
#pragma unroll
            for (int mi = 0; mi < 4; mi++)
#pragma unroll
                for (int ni = 0; ni < 4; ni++)
                    mma16816(acc[mi][ni], Af[mi], Bf[ni]);
        }

        if (t == NCONV - 1) {
#pragma unroll
            for (int ni = 0; ni < 4; ni++) {
                int col = warpN * 32 + ni * 8 + 2 * (lane & 3);
                float b0 = __ldg(bconv + col), b1 = __ldg(bconv + col + 1);
#pragma unroll
                for (int mi = 0; mi < 4; mi++) {
                    acc[mi][ni][0] = elu1(acc[mi][ni][0] + b0);
                    acc[mi][ni][1] = elu1(acc[mi][ni][1] + b1);
                    acc[mi][ni][2] = elu1(acc[mi][ni][2] + b0);
                    acc[mi][ni][3] = elu1(acc[mi][ni][3] + b1);
                }
            }
        }
    }

    // ---- epilogue: out = acc + b_skip ----
#pragma unroll
    for (int ni = 0; ni < 4; ni++) {
        int col = warpN * 32 + ni * 8 + 2 * (lane & 3);
        float b0 = __ldg(bskip + col), b1 = __ldg(bskip + col + 1);
#pragma unroll
        for (int mi = 0; mi < 4; mi++) {
            size_t r0 = mrow0 + warpM * 64 + mi * 16 + (lane >> 2);
            float2 v0 = make_float2(acc[mi][ni][0] + b0, acc[mi][ni][1] + b1);
            float2 v1 = make_float2(acc[mi][ni][2] + b0, acc[mi][ni][3] + b1);
            *(float2*)&out[r0 * Cc + col]       = v0;
            *(float2*)&out[(r0 + 8) * Cc + col] = v1;
        }
    }
}

// ---------------- launch ----------------
extern "C" void kernel_launch(void* const* d_in, const int* in_sizes, int n_in,
                              void* d_out, int out_size)
{
    const float* x   = (const float*)d_in[0];
    const int*   idx = (const int*)  d_in[1];
    const float* P   = (const float*)d_in[2];
    const float* Wc  = (const float*)d_in[3];
    const float* bc  = (const float*)d_in[4];
    const float* Ws  = (const float*)d_in[5];
    const float* bs  = (const float*)d_in[6];
    float* out = (float*)d_out;
    (void)in_sizes; (void)n_in; (void)out_size;

    cudaFuncSetAttribute(fused_mma, cudaFuncAttributeMaxDynamicSharedMemorySize, SMEM_B);

    cvt_x<<<(int)(((size_t)Mm * Cc / 4 + 255) / 256), 256>>>(x);   // must precede fused_mma
    cvt_w<<<(Cc * Ffull + 255) / 256, 256>>>(Wc, Ws);
    fused_mma<<<Mm / 128, 256, SMEM_B>>>(idx, P, bc, bs, out);
}